// round 6
// baseline (speedup 1.0000x reference)
#include <cuda_runtime.h>
#include <cuda_fp16.h>
#include <cuda_fp8.h>
#include <stdint.h>
#include <math.h>

// Problem constants (fixed by dataset)
#define Bsz  8
#define Qlen 2048
#define Klen 2048
#define Hdim 128
#define BM   64          // queries per CTA
#define BN   64          // keys per tile
#define NT   128         // 4 warps
#define NTILE (Klen / BN)

#define KTOT (Bsz * Klen * Hdim)   // 2,097,152 elements

// Pre-split history scratch, row-major [b][key][h]:
//   g_khi : fp16 hi
//   g_klo8: e4m3( (k - hi) * 4096 )
//   g_khi8: e4m3( hi )
__device__ __align__(16) __half  g_khi[KTOT];
__device__ __align__(16) uint8_t g_klo8[KTOT];
__device__ __align__(16) uint8_t g_khi8[KTOT];

// smem buffer: [hi fp16 swizzled 16KB][lo8 64x144][hi8 64x144]; double buffered
#define OFF_LO8   16384
#define OFF_HI8   (16384 + 9216)
#define TILE_BYTES (16384 + 9216 + 9216)   // 34816 (1024-aligned)
#define SMEM_BYTES (2 * TILE_BYTES)
#define T8STR 144                           // fp8 tile row stride (bank-rotating)

#define SCL   4096.0f
#define INVSCL 2.44140625e-4f               // 2^-12

__device__ __forceinline__ uint32_t smem_u32(const void* p) {
    uint32_t a;
    asm("{ .reg .u64 t; cvta.to.shared.u64 t, %1; cvt.u32.u64 %0, t; }" : "=r"(a) : "l"(p));
    return a;
}
__device__ __forceinline__ uint32_t h2u(__half2 h) { return *reinterpret_cast<uint32_t*>(&h); }

// fp32 pair -> fp16 hi + fp16 residual(lo), packed half2
__device__ __forceinline__ void split_h2(float x, float y, uint32_t& hi, uint32_t& lo) {
    __half2 h = __floats2half2_rn(x, y);
    float rx = x - __half2float(__low2half(h));
    float ry = y - __half2float(__high2half(h));
    __half2 l = __floats2half2_rn(rx, ry);
    hi = h2u(h); lo = h2u(l);
}

__device__ __forceinline__ uint32_t pk8(float a, float b, float c, float d) {
    float4 v = make_float4(a, b, c, d);
    __nv_fp8x4_e4m3 p(v);
    return *reinterpret_cast<uint32_t*>(&p);
}

// XOR-swizzled fp16 tile offset: row in [0,64), bytecol in [0,256)
__device__ __forceinline__ uint32_t swz2(int row, int bytecol) {
    int ch = bytecol >> 4;
    int chs = (ch & 8) | ((ch ^ row) & 7);
    return (uint32_t)(row * 256 + (chs << 4));
}

__device__ __forceinline__ void cpa16(uint32_t dst, const void* src) {
    asm volatile("cp.async.cg.shared.global [%0], [%1], 16;" :: "r"(dst), "l"(src));
}
#define CP_COMMIT() asm volatile("cp.async.commit_group;" ::: "memory")
#define CP_WAIT0()  asm volatile("cp.async.wait_group 0;" ::: "memory")

__device__ __forceinline__ void ldsm_x4(uint32_t& r0, uint32_t& r1, uint32_t& r2, uint32_t& r3,
                                        uint32_t addr) {
    asm volatile("ldmatrix.sync.aligned.m8n8.x4.shared.b16 {%0,%1,%2,%3}, [%4];"
                 : "=r"(r0), "=r"(r1), "=r"(r2), "=r"(r3) : "r"(addr));
}
__device__ __forceinline__ void ldsm_x4_t(uint32_t& r0, uint32_t& r1, uint32_t& r2, uint32_t& r3,
                                          uint32_t addr) {
    asm volatile("ldmatrix.sync.aligned.m8n8.x4.trans.shared.b16 {%0,%1,%2,%3}, [%4];"
                 : "=r"(r0), "=r"(r1), "=r"(r2), "=r"(r3) : "r"(addr));
}
// D(16x8,f32) += A(16x16,f16) * B(16x8,f16)
__device__ __forceinline__ void mma16816(float* d, const uint32_t* a, uint32_t b0, uint32_t b1) {
    asm volatile("mma.sync.aligned.m16n8k16.row.col.f32.f16.f16.f32 "
                 "{%0,%1,%2,%3}, {%4,%5,%6,%7}, {%8,%9}, {%0,%1,%2,%3};"
                 : "+f"(d[0]), "+f"(d[1]), "+f"(d[2]), "+f"(d[3])
                 : "r"(a[0]), "r"(a[1]), "r"(a[2]), "r"(a[3]), "r"(b0), "r"(b1));
}
// D(16x8,f32) += A(16x32,e4m3) * B(32x8,e4m3)
__device__ __forceinline__ void mma_fp8(float* d, const uint32_t* a, uint32_t b0, uint32_t b1) {
    asm volatile("mma.sync.aligned.m16n8k32.row.col.f32.e4m3.e4m3.f32 "
                 "{%0,%1,%2,%3}, {%4,%5,%6,%7}, {%8,%9}, {%0,%1,%2,%3};"
                 : "+f"(d[0]), "+f"(d[1]), "+f"(d[2]), "+f"(d[3])
                 : "r"(a[0]), "r"(a[1]), "r"(a[2]), "r"(a[3]), "r"(b0), "r"(b1));
}

// ---------------- Pre-pass: split history fp32 -> fp16 hi + fp8 cross operands ----------------
__global__ __launch_bounds__(256)
void prep_split(const float* __restrict__ history)
{
    const size_t i = ((size_t)blockIdx.x * 256 + threadIdx.x) * 8;
    float4 a = *(const float4*)(history + i);
    float4 b = *(const float4*)(history + i + 4);

    float x[8] = {a.x, a.y, a.z, a.w, b.x, b.y, b.z, b.w};
    float hf[8], lf[8];
    uint32_t hh[4];
    #pragma unroll
    for (int j = 0; j < 4; ++j) {
        __half2 h = __floats2half2_rn(x[2*j], x[2*j+1]);
        hf[2*j]   = __half2float(__low2half(h));
        hf[2*j+1] = __half2float(__high2half(h));
        lf[2*j]   = x[2*j]   - hf[2*j];
        lf[2*j+1] = x[2*j+1] - hf[2*j+1];
        hh[j] = h2u(h);
    }
    *(uint4*)(g_khi + i) = make_uint4(hh[0], hh[1], hh[2], hh[3]);
    *(uint2*)(g_klo8 + i) = make_uint2(
        pk8(lf[0]*SCL, lf[1]*SCL, lf[2]*SCL, lf[3]*SCL),
        pk8(lf[4]*SCL, lf[5]*SCL, lf[6]*SCL, lf[7]*SCL));
    *(uint2*)(g_khi8 + i) = make_uint2(
        pk8(hf[0], hf[1], hf[2], hf[3]),
        pk8(hf[4], hf[5], hf[6], hf[7]));
}

// ---------------- Main attention kernel ----------------
__global__ __launch_bounds__(NT, 2)
void attn_hmma(const float* __restrict__ out_state,
               float* __restrict__ out)
{
    extern __shared__ __align__(16) char smb[];
    const uint32_t s_base = smem_u32(smb);

    const int t    = threadIdx.x;
    const int wm   = t >> 5;          // warp id = query-row group
    const int lane = t & 31;
    const int g    = lane >> 2;       // row within fragment group (0..7)
    const int tc   = lane & 3;        // col group within row
    const int q0   = blockIdx.x * BM;
    const int b    = blockIdx.y;

    const float*   q_g   = out_state + (size_t)b * Qlen * Hdim;
    const __half*  khiB  = g_khi  + (size_t)b * Klen * Hdim;
    const uint8_t* klo8B = g_klo8 + (size_t)b * Klen * Hdim;
    const uint8_t* khi8B = g_khi8 + (size_t)b * Klen * Hdim;
    float*         o_g   = out + (size_t)b * Qlen * Hdim;

    // ---- Q fragments: fp16 hi (pass 1) + fp8 hi/lo (cross pass) ----
    uint32_t qhi[8][4];      // fp16 A-frags, k16 steps
    uint32_t q8a[4][4];      // e4m3(Qhi), k32 steps
    uint32_t q8b[4][4];      // e4m3(Qlo*4096), k32 steps
    {
        const float* qb = q_g + (size_t)(q0 + wm * 16 + g) * Hdim;

        // fp16 frags (positions h = kk*16 + tc*2 (+8), rows g and g+8)
        #pragma unroll
        for (int kk = 0; kk < 8; ++kk) {
            const int h0 = kk * 16 + tc * 2;
            float2 x00 = *(const float2*)(qb + h0);
            float2 x10 = *(const float2*)(qb + 8 * Hdim + h0);
            float2 x01 = *(const float2*)(qb + h0 + 8);
            float2 x11 = *(const float2*)(qb + 8 * Hdim + h0 + 8);
            x00.x = tanhf(x00.x); x00.y = tanhf(x00.y);
            x10.x = tanhf(x10.x); x10.y = tanhf(x10.y);
            x01.x = tanhf(x01.x); x01.y = tanhf(x01.y);
            x11.x = tanhf(x11.x); x11.y = tanhf(x11.y);
            uint32_t dum;
            split_h2(x00.x, x00.y, qhi[kk][0], dum);
            split_h2(x10.x, x10.y, qhi[kk][1], dum);
            split_h2(x01.x, x01.y, qhi[kk][2], dum);
            split_h2(x11.x, x11.y, qhi[kk][3], dum);
        }

        // fp8 frags (positions h = kq*32 + tc*4 (+16), rows g and g+8)
        #pragma unroll
        for (int kq = 0; kq < 4; ++kq) {
            const int h0 = kq * 32 + tc * 4;
            float4 va = *(const float4*)(qb + h0);
            float4 vb = *(const float4*)(qb + h0 + 16);
            float4 vc = *(const float4*)(qb + 8 * Hdim + h0);
            float4 vd = *(const float4*)(qb + 8 * Hdim + h0 + 16);
            float e[4][4] = {{va.x,va.y,va.z,va.w},{vc.x,vc.y,vc.z,vc.w},
                             {vb.x,vb.y,vb.z,vb.w},{vd.x,vd.y,vd.z,vd.w}};
            #pragma unroll
            for (int r = 0; r < 4; ++r) {
                float hf[4], lf[4];
                #pragma unroll
                for (int c = 0; c < 4; ++c) {
                    float tq = tanhf(e[r][c]);
                    hf[c] = __half2float(__float2half_rn(tq));
                    lf[c] = (tq - hf[c]) * SCL;
                }
                q8a[kq][r] = pk8(hf[0], hf[1], hf[2], hf[3]);
                q8b[kq][r] = pk8(lf[0], lf[1], lf[2], lf[3]);
            }
        }
    }

    // O accumulator: 16 h-tiles x 4 f32 (rows g, g+8)
    float o[16][4];
    #pragma unroll
    for (int n = 0; n < 16; ++n)
        #pragma unroll
        for (int j = 0; j < 4; ++j) o[n][j] = 0.f;

    float m0 = -INFINITY, m1 = -INFINITY, l0 = 0.f, l1 = 0.f;

    // ---- tile loader (hi fp16 swizzled + fp8 tiles at stride 144) ----
    auto load_tile = [&](int kt, uint32_t sb) {
        const __half*  srcH = khiB  + (size_t)kt * BN * Hdim;
        const uint8_t* srcL = klo8B + (size_t)kt * BN * Hdim;
        const uint8_t* srcG = khi8B + (size_t)kt * BN * Hdim;
        #pragma unroll
        for (int j = 0; j < 8; ++j) {
            const int idx = j * NT + t;        // 0..1023
            const int row = idx >> 4;
            const int ch  = idx & 15;
            cpa16(sb + swz2(row, ch << 4), srcH + (size_t)row * Hdim + ch * 8);
        }
        #pragma unroll
        for (int j = 0; j < 4; ++j) {
            const int idx = j * NT + t;        // 0..511
            const int row = idx >> 3;
            const int ch  = idx & 7;
            cpa16(sb + OFF_LO8 + row * T8STR + ch * 16, srcL + (size_t)row * Hdim + ch * 16);
            cpa16(sb + OFF_HI8 + row * T8STR + ch * 16, srcG + (size_t)row * Hdim + ch * 16);
        }
        CP_COMMIT();
    };

    load_tile(0, s_base);

    for (int kt = 0; kt < NTILE; ++kt) {
        CP_WAIT0();
        __syncthreads();   // tile kt visible; all warps done with the other buffer

        if (kt + 1 < NTILE)
            load_tile(kt + 1, s_base + ((kt + 1) & 1) * TILE_BYTES);

        const uint32_t s_hi = s_base + (kt & 1) * TILE_BYTES;
        const char*    bufc = smb + (size_t)((kt & 1) * TILE_BYTES);

        // ---- QK^T pass 1: fp16 Qhi . Khi ----
        float s[8][4];
        #pragma unroll
        for (int n = 0; n < 8; ++n)
            #pragma unroll
            for (int j = 0; j < 4; ++j) s[n][j] = 0.f;

        #pragma unroll
        for (int kk = 0; kk < 8; ++kk) {
            uint32_t bh[4][4];
            #pragma unroll
            for (int np = 0; np < 4; ++np) {
                const int row = np * 16 + (lane & 7) + ((lane >> 4) << 3);
                const int col = kk * 32 + ((lane >> 3) & 1) * 16;   // bytes
                ldsm_x4(bh[np][0], bh[np][1], bh[np][2], bh[np][3], s_hi + swz2(row, col));
            }
            #pragma unroll
            for (int n = 0; n < 8; ++n)
                mma16816(s[n], qhi[kk], bh[n >> 1][(n & 1) * 2], bh[n >> 1][(n & 1) * 2 + 1]);
        }

        // ---- QK^T pass 2 (fp8): s2 = Qhi8*(Klo*2^12)8 + (Qlo*2^12)8*Khi8 ----
        float s2[8][4];
        #pragma unroll
        for (int n = 0; n < 8; ++n)
            #pragma unroll
            for (int j = 0; j < 4; ++j) s2[n][j] = 0.f;

        #pragma unroll
        for (int kq = 0; kq < 4; ++kq) {
            #pragma unroll
            for (int n = 0; n < 8; ++n) {
                const uint32_t off = (uint32_t)((n * 8 + (lane >> 2)) * T8STR + kq * 32 + tc * 4);
                uint32_t b0 = *(const uint32_t*)(bufc + OFF_LO8 + off);
                uint32_t b1 = *(const uint32_t*)(bufc + OFF_LO8 + off + 16);
                mma_fp8(s2[n], q8a[kq], b0, b1);
                uint32_t c0 = *(const uint32_t*)(bufc + OFF_HI8 + off);
                uint32_t c1 = *(const uint32_t*)(bufc + OFF_HI8 + off + 16);
                mma_fp8(s2[n], q8b[kq], c0, c1);
            }
        }
        #pragma unroll
        for (int n = 0; n < 8; ++n)
            #pragma unroll
            for (int j = 0; j < 4; ++j) s[n][j] = fmaf(s2[n][j], INVSCL, s[n][j]);

        // ---- Online softmax (warp-local: each warp owns the full key range) ----
        float t0 = -INFINITY, t1 = -INFINITY;
        #pragma unroll
        for (int n = 0; n < 8; ++n) {
            t0 = fmaxf(t0, fmaxf(s[n][0], s[n][1]));
            t1 = fmaxf(t1, fmaxf(s[n][2], s[n][3]));
        }
        t0 = fmaxf(t0, __shfl_xor_sync(0xffffffffu, t0, 1));
        t0 = fmaxf(t0, __shfl_xor_sync(0xffffffffu, t0, 2));
        t1 = fmaxf(t1, __shfl_xor_sync(0xffffffffu, t1, 1));
        t1 = fmaxf(t1, __shfl_xor_sync(0xffffffffu, t1, 2));

        const float mn0 = fmaxf(m0, t0), mn1 = fmaxf(m1, t1);
        const float al0 = __expf(m0 - mn0), al1 = __expf(m1 - mn1);
        m0 = mn0; m1 = mn1;

        float rs0 = 0.f, rs1 = 0.f;
        #pragma unroll
        for (int n = 0; n < 8; ++n) {
            s[n][0] = __expf(s[n][0] - mn0);
            s[n][1] = __expf(s[n][1] - mn0);
            s[n][2] = __expf(s[n][2] - mn1);
            s[n][3] = __expf(s[n][3] - mn1);
            rs0 += s[n][0] + s[n][1];
            rs1 += s[n][2] + s[n][3];
        }
        rs0 += __shfl_xor_sync(0xffffffffu, rs0, 1);
        rs0 += __shfl_xor_sync(0xffffffffu, rs0, 2);
        rs1 += __shfl_xor_sync(0xffffffffu, rs1, 1);
        rs1 += __shfl_xor_sync(0xffffffffu, rs1, 2);
        l0 = l0 * al0 + rs0;
        l1 = l1 * al1 + rs1;

        // P A-fragments (fp16; P in [0,1], single-pass PV is accurate enough)
        uint32_t pa[4][4];
        #pragma unroll
        for (int kk = 0; kk < 4; ++kk) {
            pa[kk][0] = h2u(__floats2half2_rn(s[2*kk][0],   s[2*kk][1]));
            pa[kk][1] = h2u(__floats2half2_rn(s[2*kk][2],   s[2*kk][3]));
            pa[kk][2] = h2u(__floats2half2_rn(s[2*kk+1][0], s[2*kk+1][1]));
            pa[kk][3] = h2u(__floats2half2_rn(s[2*kk+1][2], s[2*kk+1][3]));
        }

        // rescale O by alpha
        #pragma unroll
        for (int n = 0; n < 16; ++n) {
            o[n][0] *= al0; o[n][1] *= al0;
            o[n][2] *= al1; o[n][3] *= al1;
        }

        // ---- PV: O += P * V (V = same smem bytes as K-hi, via ldmatrix.trans) ----
        #pragma unroll
        for (int kg = 0; kg < 4; ++kg) {
            #pragma unroll
            for (int hp = 0; hp < 8; ++hp) {
                const int row = kg * 16 + (lane & 7) + (((lane >> 3) & 1) << 3);
                const int col = hp * 32 + ((lane >> 4) & 1) * 16;
                uint32_t r0, r1, r2, r3;
                ldsm_x4_t(r0, r1, r2, r3, s_hi + swz2(row, col));
                mma16816(o[2*hp],     pa[kg], r0, r1);
                mma16816(o[2*hp + 1], pa[kg], r2, r3);
            }
        }
    }

    // ---- Epilogue: normalize and store ----
    const float inv0 = 1.0f / l0;
    const float inv1 = 1.0f / l1;
    float* ob = o_g + (size_t)(q0 + wm * 16 + g) * Hdim;
    #pragma unroll
    for (int n = 0; n < 16; ++n) {
        const int h = n * 8 + tc * 2;
        *(float2*)(ob + h)            = make_float2(o[n][0] * inv0, o[n][1] * inv0);
        *(float2*)(ob + 8 * Hdim + h) = make_float2(o[n][2] * inv1, o[n][3] * inv1);
    }
}

extern "C" void kernel_launch(void* const* d_in, const int* in_sizes, int n_in,
                              void* d_out, int out_size)
{
    const float* out_state = (const float*)d_in[0];
    const float* history   = (const float*)d_in[1];
    float*       out       = (float*)d_out;

    // 1) split history fp32 -> fp16 hi + fp8 cross operands
    prep_split<<<KTOT / 8 / 256, 256>>>(history);

    // 2) fused flash attention on HMMA (fp16 main pass + fp8 correction pass)
    cudaFuncSetAttribute(attn_hmma, cudaFuncAttributeMaxDynamicSharedMemorySize, SMEM_BYTES);
    dim3 grid(Qlen / BM, Bsz);
    attn_hmma<<<grid, NT, SMEM_BYTES>>>(out_state, out);
}

// round 8
// speedup vs baseline: 1.2729x; 1.2729x over previous
#include <cuda_runtime.h>
#include <cuda_fp16.h>
#include <stdint.h>
#include <math.h>

// Problem constants (fixed by dataset)
#define Bsz  8
#define Qlen 2048
#define Klen 2048
#define Hdim 128
#define BM   64          // queries per CTA
#define BN   64          // keys per tile
#define NT   128         // 4 warps
#define NTILE (Klen / BN)
#define NS   3           // pipeline stages

#define KTOT (Bsz * Klen * Hdim)   // 2,097,152 elements

// Pre-split history scratch (fp16 hi + residual lo), row-major [b][key][h]
__device__ __align__(16) __half g_khi[KTOT];
__device__ __align__(16) __half g_klo[KTOT];

// stage: [hi fp16 swizzled 16KB][lo fp16 swizzled 16KB]
#define TILE_HI_BYTES 16384
#define TILE_BYTES    32768
#define SMEM_BYTES    (NS * TILE_BYTES)   // 96 KB -> 2 CTAs/SM

#define LOG2E 1.4426950408889634f

__device__ __forceinline__ uint32_t smem_u32(const void* p) {
    uint32_t a;
    asm("{ .reg .u64 t; cvta.to.shared.u64 t, %1; cvt.u32.u64 %0, t; }" : "=r"(a) : "l"(p));
    return a;
}
__device__ __forceinline__ uint32_t h2u(__half2 h) { return *reinterpret_cast<uint32_t*>(&h); }
__device__ __forceinline__ float ex2f(float x) {
    float y; asm("ex2.approx.ftz.f32 %0, %1;" : "=f"(y) : "f"(x)); return y;
}

// fp32 pair -> fp16 hi + fp16 residual(lo), packed half2
__device__ __forceinline__ void split_h2(float x, float y, uint32_t& hi, uint32_t& lo) {
    __half2 h = __floats2half2_rn(x, y);
    float rx = x - __half2float(__low2half(h));
    float ry = y - __half2float(__high2half(h));
    __half2 l = __floats2half2_rn(rx, ry);
    hi = h2u(h); lo = h2u(l);
}

// XOR-swizzled tile offset: row in [0,64), bytecol in [0,256)
__device__ __forceinline__ uint32_t swz2(int row, int bytecol) {
    int ch = bytecol >> 4;
    int chs = (ch & 8) | ((ch ^ row) & 7);
    return (uint32_t)(row * 256 + (chs << 4));
}

__device__ __forceinline__ void cpa16(uint32_t dst, const void* src) {
    asm volatile("cp.async.cg.shared.global [%0], [%1], 16;" :: "r"(dst), "l"(src));
}

// ---- mbarrier ops (sm_80-level, family-generic safe) ----
#define MBAR_INIT(mb, c) \
    asm volatile("mbarrier.init.shared.b64 [%0], %1;" :: "r"((uint32_t)(mb)), "r"((uint32_t)(c)) : "memory")
#define MBAR_ARRIVE(mb) \
    asm volatile("mbarrier.arrive.shared.b64 _, [%0];" :: "r"((uint32_t)(mb)) : "memory")
// .noinc: consume one of the init-count arrivals when this thread's prior cp.asyncs land
#define CP_MBAR_ARRIVE(mb) \
    asm volatile("cp.async.mbarrier.arrive.noinc.shared.b64 [%0];" :: "r"((uint32_t)(mb)) : "memory")
#define MBAR_WAIT(mb, par) do { \
    uint32_t _mb = (uint32_t)(mb); uint32_t _p = (uint32_t)(par); uint32_t _done; \
    asm volatile("{\n\t.reg .pred p;\n\t" \
        "mbarrier.try_wait.parity.shared.b64 p, [%1], %2;\n\t" \
        "selp.b32 %0, 1, 0, p;\n\t}" : "=r"(_done) : "r"(_mb), "r"(_p) : "memory"); \
    while (!_done) { \
        asm volatile("{\n\t.reg .pred p;\n\t" \
            "mbarrier.try_wait.parity.shared.b64 p, [%1], %2;\n\t" \
            "selp.b32 %0, 1, 0, p;\n\t}" : "=r"(_done) : "r"(_mb), "r"(_p) : "memory"); \
    } \
} while (0)

__device__ __forceinline__ void ldsm_x4(uint32_t& r0, uint32_t& r1, uint32_t& r2, uint32_t& r3,
                                        uint32_t addr) {
    asm volatile("ldmatrix.sync.aligned.m8n8.x4.shared.b16 {%0,%1,%2,%3}, [%4];"
                 : "=r"(r0), "=r"(r1), "=r"(r2), "=r"(r3) : "r"(addr));
}
__device__ __forceinline__ void ldsm_x4_t(uint32_t& r0, uint32_t& r1, uint32_t& r2, uint32_t& r3,
                                          uint32_t addr) {
    asm volatile("ldmatrix.sync.aligned.m8n8.x4.trans.shared.b16 {%0,%1,%2,%3}, [%4];"
                 : "=r"(r0), "=r"(r1), "=r"(r2), "=r"(r3) : "r"(addr));
}
// D(16x8,f32) += A(16x16,f16) * B(16x8,f16)
__device__ __forceinline__ void mma16816(float* d, const uint32_t* a, uint32_t b0, uint32_t b1) {
    asm volatile("mma.sync.aligned.m16n8k16.row.col.f32.f16.f16.f32 "
                 "{%0,%1,%2,%3}, {%4,%5,%6,%7}, {%8,%9}, {%0,%1,%2,%3};"
                 : "+f"(d[0]), "+f"(d[1]), "+f"(d[2]), "+f"(d[3])
                 : "r"(a[0]), "r"(a[1]), "r"(a[2]), "r"(a[3]), "r"(b0), "r"(b1));
}

// ---------------- Pre-pass: split history fp32 -> fp16 hi/lo ----------------
__global__ __launch_bounds__(256)
void prep_split(const float* __restrict__ history)
{
    const size_t i = ((size_t)blockIdx.x * 256 + threadIdx.x) * 8;
    float4 a = *(const float4*)(history + i);
    float4 b = *(const float4*)(history + i + 4);
    uint32_t h[4], l[4];
    split_h2(a.x, a.y, h[0], l[0]);
    split_h2(a.z, a.w, h[1], l[1]);
    split_h2(b.x, b.y, h[2], l[2]);
    split_h2(b.z, b.w, h[3], l[3]);
    *(uint4*)(g_khi + i) = make_uint4(h[0], h[1], h[2], h[3]);
    *(uint4*)(g_klo + i) = make_uint4(l[0], l[1], l[2], l[3]);
}

// ---------------- Main attention kernel ----------------
__global__ __launch_bounds__(NT, 2)
void attn_hmma(const float* __restrict__ out_state,
               float* __restrict__ out)
{
    extern __shared__ __align__(16) char smb[];
    __shared__ __align__(16) uint64_t mbar[2 * NS];   // [0..NS) full, [NS..2NS) empty
    const uint32_t s_base  = smem_u32(smb);
    const uint32_t mb_base = smem_u32(mbar);

    const int t    = threadIdx.x;
    const int wm   = t >> 5;          // warp id = query-row group (0..3)
    const int lane = t & 31;
    const int g    = lane >> 2;       // row within fragment group (0..7)
    const int tc   = lane & 3;        // col pair within group
    const int q0   = blockIdx.x * BM;
    const int b    = blockIdx.y;

    const float*  q_g  = out_state + (size_t)b * Qlen * Hdim;
    const __half* khiB = g_khi + (size_t)b * Klen * Hdim;
    const __half* kloB = g_klo + (size_t)b * Klen * Hdim;
    float*        o_g  = out + (size_t)b * Qlen * Hdim;

    // ---- init barriers ----
    if (t == 0) {
        #pragma unroll
        for (int s = 0; s < 2 * NS; ++s) MBAR_INIT(mb_base + s * 8, NT);
    }
    __syncthreads();

    // ---- producer helper: this thread's share of tile j into stage s ----
    auto produce = [&](int j, int s) {
        const uint32_t sb = s_base + (uint32_t)s * TILE_BYTES;
        const __half* srcH = khiB + (size_t)j * BN * Hdim;
        const __half* srcL = kloB + (size_t)j * BN * Hdim;
        #pragma unroll
        for (int jj = 0; jj < 8; ++jj) {
            const int idx = jj * NT + t;       // 0..1023
            const int row = idx >> 4;
            const int ch  = idx & 15;
            const uint32_t d = sb + swz2(row, ch << 4);
            cpa16(d,                 srcH + (size_t)row * Hdim + ch * 8);
            cpa16(d + TILE_HI_BYTES, srcL + (size_t)row * Hdim + ch * 8);
        }
        CP_MBAR_ARRIVE(mb_base + s * 8);       // full[s]: arrives when my copies land
    };

    // ---- Q A-fragments: tanh, scale by log2e, split fp16 hi/lo ----
    uint32_t qhi[8][4], qlo[8][4];
    {
        const float* qb = q_g + (size_t)(q0 + wm * 16 + g) * Hdim;
        #pragma unroll
        for (int kk = 0; kk < 8; ++kk) {
            const int h0 = kk * 16 + tc * 2;
            float2 x00 = *(const float2*)(qb + h0);
            float2 x10 = *(const float2*)(qb + 8 * Hdim + h0);
            float2 x01 = *(const float2*)(qb + h0 + 8);
            float2 x11 = *(const float2*)(qb + 8 * Hdim + h0 + 8);
            x00.x = tanhf(x00.x) * LOG2E; x00.y = tanhf(x00.y) * LOG2E;
            x10.x = tanhf(x10.x) * LOG2E; x10.y = tanhf(x10.y) * LOG2E;
            x01.x = tanhf(x01.x) * LOG2E; x01.y = tanhf(x01.y) * LOG2E;
            x11.x = tanhf(x11.x) * LOG2E; x11.y = tanhf(x11.y) * LOG2E;
            split_h2(x00.x, x00.y, qhi[kk][0], qlo[kk][0]);
            split_h2(x10.x, x10.y, qhi[kk][1], qlo[kk][1]);
            split_h2(x01.x, x01.y, qhi[kk][2], qlo[kk][2]);
            split_h2(x11.x, x11.y, qhi[kk][3], qlo[kk][3]);
        }
    }

    // O accumulator: 16 h-tiles x 4 f32 (rows g, g+8)
    float o[16][4];
    #pragma unroll
    for (int n = 0; n < 16; ++n)
        #pragma unroll
        for (int j = 0; j < 4; ++j) o[n][j] = 0.f;

    float m0 = -INFINITY, m1 = -INFINITY, l0 = 0.f, l1 = 0.f;

    // ---- pipeline cursors ----
    int pst = 0, pph = 1;   // producer cursor over empty[] (phase 1: fresh barriers pass)
    int cst = 0, cph = 0;   // consumer cursor over full[]

    // prologue: produce tiles 0..NS-2
    #pragma unroll
    for (int j = 0; j < NS - 1; ++j) {
        MBAR_WAIT(mb_base + (NS + pst) * 8, pph);
        produce(j, pst);
        if (++pst == NS) { pst = 0; pph ^= 1; }
    }

    for (int kt = 0; kt < NTILE; ++kt) {
        // produce tile kt+NS-1
        if (kt + NS - 1 < NTILE) {
            MBAR_WAIT(mb_base + (NS + pst) * 8, pph);
            produce(kt + NS - 1, pst);
            if (++pst == NS) { pst = 0; pph ^= 1; }
        }

        // consume tile kt
        MBAR_WAIT(mb_base + cst * 8, cph);
        const uint32_t s_hi = s_base + (uint32_t)cst * TILE_BYTES;
        const uint32_t s_lo = s_hi + TILE_HI_BYTES;

        // ---- QK^T: S (16x64 per warp), 3-pass split for fp32 accuracy ----
        float s[8][4];
        #pragma unroll
        for (int n = 0; n < 8; ++n)
            #pragma unroll
            for (int j = 0; j < 4; ++j) s[n][j] = 0.f;

        #pragma unroll
        for (int kk = 0; kk < 8; ++kk) {
            uint32_t bh[4][4], bl[4][4];
            #pragma unroll
            for (int np = 0; np < 4; ++np) {
                const int row = np * 16 + (lane & 7) + ((lane >> 4) << 3);
                const int col = kk * 32 + ((lane >> 3) & 1) * 16;   // bytes
                const uint32_t a = swz2(row, col);
                ldsm_x4(bh[np][0], bh[np][1], bh[np][2], bh[np][3], s_hi + a);
                ldsm_x4(bl[np][0], bl[np][1], bl[np][2], bl[np][3], s_lo + a);
            }
            #pragma unroll
            for (int n = 0; n < 8; ++n)
                mma16816(s[n], qhi[kk], bh[n >> 1][(n & 1) * 2], bh[n >> 1][(n & 1) * 2 + 1]);
            #pragma unroll
            for (int n = 0; n < 8; ++n)
                mma16816(s[n], qhi[kk], bl[n >> 1][(n & 1) * 2], bl[n >> 1][(n & 1) * 2 + 1]);
            #pragma unroll
            for (int n = 0; n < 8; ++n)
                mma16816(s[n], qlo[kk], bh[n >> 1][(n & 1) * 2], bh[n >> 1][(n & 1) * 2 + 1]);
        }

        // ---- Online softmax in base-2 domain (warp-local) ----
        float t0 = -INFINITY, t1 = -INFINITY;
        #pragma unroll
        for (int n = 0; n < 8; ++n) {
            t0 = fmaxf(t0, fmaxf(s[n][0], s[n][1]));
            t1 = fmaxf(t1, fmaxf(s[n][2], s[n][3]));
        }
        t0 = fmaxf(t0, __shfl_xor_sync(0xffffffffu, t0, 1));
        t0 = fmaxf(t0, __shfl_xor_sync(0xffffffffu, t0, 2));
        t1 = fmaxf(t1, __shfl_xor_sync(0xffffffffu, t1, 1));
        t1 = fmaxf(t1, __shfl_xor_sync(0xffffffffu, t1, 2));

        const float mn0 = fmaxf(m0, t0), mn1 = fmaxf(m1, t1);
        const float al0 = ex2f(m0 - mn0), al1 = ex2f(m1 - mn1);
        m0 = mn0; m1 = mn1;

        float rs0 = 0.f, rs1 = 0.f;
        #pragma unroll
        for (int n = 0; n < 8; ++n) {
            s[n][0] = ex2f(s[n][0] - mn0);
            s[n][1] = ex2f(s[n][1] - mn0);
            s[n][2] = ex2f(s[n][2] - mn1);
            s[n][3] = ex2f(s[n][3] - mn1);
            rs0 += s[n][0] + s[n][1];
            rs1 += s[n][2] + s[n][3];
        }
        rs0 += __shfl_xor_sync(0xffffffffu, rs0, 1);
        rs0 += __shfl_xor_sync(0xffffffffu, rs0, 2);
        rs1 += __shfl_xor_sync(0xffffffffu, rs1, 1);
        rs1 += __shfl_xor_sync(0xffffffffu, rs1, 2);
        l0 = l0 * al0 + rs0;
        l1 = l1 * al1 + rs1;

        // P A-fragments (fp16; P in [0,1])
        uint32_t pa[4][4];
        #pragma unroll
        for (int kk = 0; kk < 4; ++kk) {
            pa[kk][0] = h2u(__floats2half2_rn(s[2*kk][0],   s[2*kk][1]));
            pa[kk][1] = h2u(__floats2half2_rn(s[2*kk][2],   s[2*kk][3]));
            pa[kk][2] = h2u(__floats2half2_rn(s[2*kk+1][0], s[2*kk+1][1]));
            pa[kk][3] = h2u(__floats2half2_rn(s[2*kk+1][2], s[2*kk+1][3]));
        }

        // rescale O by alpha
        #pragma unroll
        for (int n = 0; n < 16; ++n) {
            o[n][0] *= al0; o[n][1] *= al0;
            o[n][2] *= al1; o[n][3] *= al1;
        }

        // ---- PV: O += P * V (V = same smem bytes as K-hi, via ldmatrix.trans) ----
        #pragma unroll
        for (int kg = 0; kg < 4; ++kg) {
            #pragma unroll
            for (int hp = 0; hp < 8; ++hp) {
                const int row = kg * 16 + (lane & 7) + (((lane >> 3) & 1) << 3);
                const int col = hp * 32 + ((lane >> 4) & 1) * 16;
                uint32_t r0, r1, r2, r3;
                ldsm_x4_t(r0, r1, r2, r3, s_hi + swz2(row, col));
                mma16816(o[2*hp],     pa[kg], r0, r1);
                mma16816(o[2*hp + 1], pa[kg], r2, r3);
            }
        }

        // done with this stage
        MBAR_ARRIVE(mb_base + (NS + cst) * 8);
        if (++cst == NS) { cst = 0; cph ^= 1; }
    }

    // ---- Epilogue: normalize and store ----
    const float inv0 = 1.0f / l0;
    const float inv1 = 1.0f / l1;
    float* ob = o_g + (size_t)(q0 + wm * 16 + g) * Hdim;
    #pragma unroll
    for (int n = 0; n < 16; ++n) {
        const int h = n * 8 + tc * 2;
        *(float2*)(ob + h)            = make_float2(o[n][0] * inv0, o[n][1] * inv0);
        *(float2*)(ob + 8 * Hdim + h) = make_float2(o[n][2] * inv1, o[n][3] * inv1);
    }
}

extern "C" void kernel_launch(void* const* d_in, const int* in_sizes, int n_in,
                              void* d_out, int out_size)
{
    const float* out_state = (const float*)d_in[0];
    const float* history   = (const float*)d_in[1];
    float*       out       = (float*)d_out;

    // 1) split history fp32 -> fp16 hi/lo scratch
    prep_split<<<KTOT / 8 / 256, 256>>>(history);

    // 2) fused flash attention on HMMA, mbarrier-pipelined (no per-tile CTA barrier)
    cudaFuncSetAttribute(attn_hmma, cudaFuncAttributeMaxDynamicSharedMemorySize, SMEM_BYTES);
    dim3 grid(Qlen / BM, Bsz);
    attn_hmma<<<grid, NT, SMEM_BYTES>>>(out_state, out);
}

// round 9
// speedup vs baseline: 1.3875x; 1.0901x over previous
#include <cuda_runtime.h>
#include <cuda_fp16.h>
#include <stdint.h>
#include <math.h>

// Problem constants (fixed by dataset)
#define Bsz  8
#define Qlen 2048
#define Klen 2048
#define Hdim 128
#define BM   64          // queries per CTA
#define BN   64          // keys per tile
#define NT   128         // 4 warps
#define NTILE (Klen / BN)

#define KTOT (Bsz * Klen * Hdim)   // 2,097,152 elements

// Pre-split history scratch (fp16 hi + residual lo), row-major [b][key][h]
__device__ __align__(16) __half g_khi[KTOT];
__device__ __align__(16) __half g_klo[KTOT];

// smem tile: 64 rows x 128 fp16 = 16KB (hi) + 16KB (lo); double buffered = 64KB
#define TILE_HI_BYTES 16384
#define TILE_BYTES    32768
#define SMEM_BYTES    (2 * TILE_BYTES)

#define LOG2E 1.4426950408889634f
#define ONESF16X2 0x3C003C00u     // half2(1.0, 1.0)

__device__ __forceinline__ uint32_t smem_u32(const void* p) {
    uint32_t a;
    asm("{ .reg .u64 t; cvta.to.shared.u64 t, %1; cvt.u32.u64 %0, t; }" : "=r"(a) : "l"(p));
    return a;
}
__device__ __forceinline__ uint32_t h2u(__half2 h) { return *reinterpret_cast<uint32_t*>(&h); }
__device__ __forceinline__ float ex2f(float x) {
    float y; asm("ex2.approx.ftz.f32 %0, %1;" : "=f"(y) : "f"(x)); return y;
}
// packed fp16x2 2^x
__device__ __forceinline__ uint32_t ex2h2(uint32_t x) {
    uint32_t y; asm("ex2.approx.f16x2 %0, %1;" : "=r"(y) : "r"(x)); return y;
}

// fp32 pair -> fp16 hi + fp16 residual(lo), packed half2
__device__ __forceinline__ void split_h2(float x, float y, uint32_t& hi, uint32_t& lo) {
    __half2 h = __floats2half2_rn(x, y);
    float rx = x - __half2float(__low2half(h));
    float ry = y - __half2float(__high2half(h));
    __half2 l = __floats2half2_rn(rx, ry);
    hi = h2u(h); lo = h2u(l);
}

// XOR-swizzled tile offset: row in [0,64), bytecol in [0,256)
__device__ __forceinline__ uint32_t swz2(int row, int bytecol) {
    int ch = bytecol >> 4;
    int chs = (ch & 8) | ((ch ^ row) & 7);
    return (uint32_t)(row * 256 + (chs << 4));
}

__device__ __forceinline__ void cpa16(uint32_t dst, const void* src) {
    asm volatile("cp.async.cg.shared.global [%0], [%1], 16;" :: "r"(dst), "l"(src));
}
#define CP_COMMIT() asm volatile("cp.async.commit_group;" ::: "memory")
#define CP_WAIT0()  asm volatile("cp.async.wait_group 0;" ::: "memory")

__device__ __forceinline__ void ldsm_x4(uint32_t& r0, uint32_t& r1, uint32_t& r2, uint32_t& r3,
                                        uint32_t addr) {
    asm volatile("ldmatrix.sync.aligned.m8n8.x4.shared.b16 {%0,%1,%2,%3}, [%4];"
                 : "=r"(r0), "=r"(r1), "=r"(r2), "=r"(r3) : "r"(addr));
}
__device__ __forceinline__ void ldsm_x4_t(uint32_t& r0, uint32_t& r1, uint32_t& r2, uint32_t& r3,
                                          uint32_t addr) {
    asm volatile("ldmatrix.sync.aligned.m8n8.x4.trans.shared.b16 {%0,%1,%2,%3}, [%4];"
                 : "=r"(r0), "=r"(r1), "=r"(r2), "=r"(r3) : "r"(addr));
}
// D(16x8,f32) += A(16x16,f16) * B(16x8,f16)
__device__ __forceinline__ void mma16816(float* d, const uint32_t* a, uint32_t b0, uint32_t b1) {
    asm volatile("mma.sync.aligned.m16n8k16.row.col.f32.f16.f16.f32 "
                 "{%0,%1,%2,%3}, {%4,%5,%6,%7}, {%8,%9}, {%0,%1,%2,%3};"
                 : "+f"(d[0]), "+f"(d[1]), "+f"(d[2]), "+f"(d[3])
                 : "r"(a[0]), "r"(a[1]), "r"(a[2]), "r"(a[3]), "r"(b0), "r"(b1));
}

// ---------------- Pre-pass: split history fp32 -> fp16 hi/lo ----------------
__global__ __launch_bounds__(256)
void prep_split(const float* __restrict__ history)
{
    const size_t i = ((size_t)blockIdx.x * 256 + threadIdx.x) * 8;
    float4 a = *(const float4*)(history + i);
    float4 b = *(const float4*)(history + i + 4);
    uint32_t h[4], l[4];
    split_h2(a.x, a.y, h[0], l[0]);
    split_h2(a.z, a.w, h[1], l[1]);
    split_h2(b.x, b.y, h[2], l[2]);
    split_h2(b.z, b.w, h[3], l[3]);
    *(uint4*)(g_khi + i) = make_uint4(h[0], h[1], h[2], h[3]);
    *(uint4*)(g_klo + i) = make_uint4(l[0], l[1], l[2], l[3]);
}

// ---------------- Main attention kernel ----------------
__global__ __launch_bounds__(NT, 2)
void attn_hmma(const float* __restrict__ out_state,
               float* __restrict__ out)
{
    extern __shared__ __align__(16) char smb[];
    const uint32_t s_base = smem_u32(smb);

    const int t    = threadIdx.x;
    const int wm   = t >> 5;          // warp id = query-row group
    const int lane = t & 31;
    const int g    = lane >> 2;       // row within fragment group (0..7)
    const int tc   = lane & 3;        // col pair within group
    const int q0   = blockIdx.x * BM;
    const int b    = blockIdx.y;

    const float*  q_g  = out_state + (size_t)b * Qlen * Hdim;
    const __half* khiB = g_khi + (size_t)b * Klen * Hdim;
    const __half* kloB = g_klo + (size_t)b * Klen * Hdim;
    float*        o_g  = out + (size_t)b * Qlen * Hdim;

    // ---- Q A-fragments: tanh * log2e, split fp16 hi/lo ----
    uint32_t qhi[8][4], qlo[8][4];
    {
        const float* qb = q_g + (size_t)(q0 + wm * 16 + g) * Hdim;
        #pragma unroll
        for (int kk = 0; kk < 8; ++kk) {
            const int h0 = kk * 16 + tc * 2;
            float2 x00 = *(const float2*)(qb + h0);
            float2 x10 = *(const float2*)(qb + 8 * Hdim + h0);
            float2 x01 = *(const float2*)(qb + h0 + 8);
            float2 x11 = *(const float2*)(qb + 8 * Hdim + h0 + 8);
            x00.x = tanhf(x00.x) * LOG2E; x00.y = tanhf(x00.y) * LOG2E;
            x10.x = tanhf(x10.x) * LOG2E; x10.y = tanhf(x10.y) * LOG2E;
            x01.x = tanhf(x01.x) * LOG2E; x01.y = tanhf(x01.y) * LOG2E;
            x11.x = tanhf(x11.x) * LOG2E; x11.y = tanhf(x11.y) * LOG2E;
            split_h2(x00.x, x00.y, qhi[kk][0], qlo[kk][0]);
            split_h2(x10.x, x10.y, qhi[kk][1], qlo[kk][1]);
            split_h2(x01.x, x01.y, qhi[kk][2], qlo[kk][2]);
            split_h2(x11.x, x11.y, qhi[kk][3], qlo[kk][3]);
        }
    }

    // O accumulator: 16 h-tiles x 4 f32 (rows g, g+8), plus l-column accumulator
    float o[16][4];
    #pragma unroll
    for (int n = 0; n < 16; ++n)
        #pragma unroll
        for (int j = 0; j < 4; ++j) o[n][j] = 0.f;
    float ol[4] = {0.f, 0.f, 0.f, 0.f};   // ol[0]=l(row g), ol[2]=l(row g+8)

    float m0 = -INFINITY, m1 = -INFINITY;

    // ---- Prefetch tile 0 into buffer 0 ----
    {
        #pragma unroll
        for (int j = 0; j < 8; ++j) {
            const int idx = j * NT + t;        // 0..1023
            const int row = idx >> 4;
            const int ch  = idx & 15;
            const uint32_t d = s_base + swz2(row, ch << 4);
            cpa16(d,                 khiB + (size_t)row * Hdim + ch * 8);
            cpa16(d + TILE_HI_BYTES, kloB + (size_t)row * Hdim + ch * 8);
        }
        CP_COMMIT();
    }

    for (int kt = 0; kt < NTILE; ++kt) {
        CP_WAIT0();
        __syncthreads();   // tile kt visible; all warps done with the other buffer

        // ---- Prefetch tile kt+1 into the other buffer ----
        if (kt + 1 < NTILE) {
            const uint32_t sb = s_base + ((kt + 1) & 1) * TILE_BYTES;
            const __half* srcH = khiB + (size_t)(kt + 1) * BN * Hdim;
            const __half* srcL = kloB + (size_t)(kt + 1) * BN * Hdim;
            #pragma unroll
            for (int j = 0; j < 8; ++j) {
                const int idx = j * NT + t;
                const int row = idx >> 4;
                const int ch  = idx & 15;
                const uint32_t d = sb + swz2(row, ch << 4);
                cpa16(d,                 srcH + (size_t)row * Hdim + ch * 8);
                cpa16(d + TILE_HI_BYTES, srcL + (size_t)row * Hdim + ch * 8);
            }
            CP_COMMIT();
        }

        const uint32_t s_hi = s_base + (kt & 1) * TILE_BYTES;
        const uint32_t s_lo = s_hi + TILE_HI_BYTES;

        // ---- QK^T: S (16x64 per warp), 3-pass split (base-2 domain) ----
        float s[8][4];
        #pragma unroll
        for (int n = 0; n < 8; ++n)
            #pragma unroll
            for (int j = 0; j < 4; ++j) s[n][j] = 0.f;

        #pragma unroll
        for (int kk = 0; kk < 8; ++kk) {
            uint32_t bh[4][4], bl[4][4];
            #pragma unroll
            for (int np = 0; np < 4; ++np) {
                const int row = np * 16 + (lane & 7) + ((lane >> 4) << 3);
                const int col = kk * 32 + ((lane >> 3) & 1) * 16;   // bytes
                const uint32_t a = swz2(row, col);
                ldsm_x4(bh[np][0], bh[np][1], bh[np][2], bh[np][3], s_hi + a);
                ldsm_x4(bl[np][0], bl[np][1], bl[np][2], bl[np][3], s_lo + a);
            }
            #pragma unroll
            for (int n = 0; n < 8; ++n)
                mma16816(s[n], qhi[kk], bh[n >> 1][(n & 1) * 2], bh[n >> 1][(n & 1) * 2 + 1]);
            #pragma unroll
            for (int n = 0; n < 8; ++n)
                mma16816(s[n], qhi[kk], bl[n >> 1][(n & 1) * 2], bl[n >> 1][(n & 1) * 2 + 1]);
            #pragma unroll
            for (int n = 0; n < 8; ++n)
                mma16816(s[n], qlo[kk], bh[n >> 1][(n & 1) * 2], bh[n >> 1][(n & 1) * 2 + 1]);
        }

        // ---- Online max (warp-local); no sum reduction (l via ones-MMA) ----
        float t0 = -INFINITY, t1 = -INFINITY;
        #pragma unroll
        for (int n = 0; n < 8; ++n) {
            t0 = fmaxf(t0, fmaxf(s[n][0], s[n][1]));
            t1 = fmaxf(t1, fmaxf(s[n][2], s[n][3]));
        }
        t0 = fmaxf(t0, __shfl_xor_sync(0xffffffffu, t0, 1));
        t0 = fmaxf(t0, __shfl_xor_sync(0xffffffffu, t0, 2));
        t1 = fmaxf(t1, __shfl_xor_sync(0xffffffffu, t1, 1));
        t1 = fmaxf(t1, __shfl_xor_sync(0xffffffffu, t1, 2));

        const float mn0 = fmaxf(m0, t0), mn1 = fmaxf(m1, t1);
        const bool updated = (mn0 != m0) | (mn1 != m1);
        const bool any_up  = __any_sync(0xffffffffu, updated);
        const float al0 = ex2f(m0 - mn0), al1 = ex2f(m1 - mn1);
        m0 = mn0; m1 = mn1;

        // ---- p = 2^(s - m): pack to half2 then packed ex2 -> pa fragments directly ----
        uint32_t pa[4][4];
        #pragma unroll
        for (int n = 0; n < 8; ++n) {
            uint32_t ua = h2u(__floats2half2_rn(s[n][0] - mn0, s[n][1] - mn0));
            uint32_t ub = h2u(__floats2half2_rn(s[n][2] - mn1, s[n][3] - mn1));
            pa[n >> 1][(n & 1) * 2]     = ex2h2(ua);
            pa[n >> 1][(n & 1) * 2 + 1] = ex2h2(ub);
        }

        // rescale O (and l-column) by alpha only when some row max changed
        if (any_up) {
            #pragma unroll
            for (int n = 0; n < 16; ++n) {
                o[n][0] *= al0; o[n][1] *= al0;
                o[n][2] *= al1; o[n][3] *= al1;
            }
            ol[0] *= al0; ol[1] *= al0; ol[2] *= al1; ol[3] *= al1;
        }

        // ---- PV: O += P * V; l-column via constant all-ones B fragment ----
        #pragma unroll
        for (int kg = 0; kg < 4; ++kg) {
            #pragma unroll
            for (int hp = 0; hp < 8; ++hp) {
                const int row = kg * 16 + (lane & 7) + (((lane >> 3) & 1) << 3);
                const int col = hp * 32 + ((lane >> 4) & 1) * 16;
                uint32_t r0, r1, r2, r3;
                ldsm_x4_t(r0, r1, r2, r3, s_hi + swz2(row, col));
                mma16816(o[2*hp],     pa[kg], r0, r1);
                mma16816(o[2*hp + 1], pa[kg], r2, r3);
            }
            mma16816(ol, pa[kg], ONESF16X2, ONESF16X2);   // row sums -> l
        }
    }

    // ---- Epilogue: normalize by l (from ones-MMA column) and store ----
    const float inv0 = 1.0f / ol[0];
    const float inv1 = 1.0f / ol[2];
    float* ob = o_g + (size_t)(q0 + wm * 16 + g) * Hdim;
    #pragma unroll
    for (int n = 0; n < 16; ++n) {
        const int h = n * 8 + tc * 2;
        *(float2*)(ob + h)            = make_float2(o[n][0] * inv0, o[n][1] * inv0);
        *(float2*)(ob + 8 * Hdim + h) = make_float2(o[n][2] * inv1, o[n][3] * inv1);
    }
}

extern "C" void kernel_launch(void* const* d_in, const int* in_sizes, int n_in,
                              void* d_out, int out_size)
{
    const float* out_state = (const float*)d_in[0];
    const float* history   = (const float*)d_in[1];
    float*       out       = (float*)d_out;

    // 1) split history fp32 -> fp16 hi/lo scratch
    prep_split<<<KTOT / 8 / 256, 256>>>(history);

    // 2) fused flash attention on HMMA
    cudaFuncSetAttribute(attn_hmma, cudaFuncAttributeMaxDynamicSharedMemorySize, SMEM_BYTES);
    dim3 grid(Qlen / BM, Bsz);
    attn_hmma<<<grid, NT, SMEM_BYTES>>>(out_state, out);
}